// round 14
// baseline (speedup 1.0000x reference)
#include <cuda_runtime.h>
#include <cuda_fp16.h>
#include <cstdint>

#define BB 4
#define HH 16
#define SS 4096
#define DD 64
#define NHEAD (BB*HH)        // 64
#define NCH 8
#define CHUNK (SS/NCH)       // 512
#define KT 32                // s-rows per smem tile (double-buffered)
#define NT (CHUNK/KT)        // 16
#define NCTA (NHEAD*NCH)     // 512
#define NTHR 256
#define EPSF 1e-6f
#define STR 72               // padded half cols (144B row stride, conflict-free LDSM)
#define PSZ (65*64)          // partial floats: rows 0-63 kv[d][v], row 64 = k1[d]

// per-(head,chunk) partial results; fully rewritten every launch (no zeroing needed)
__device__ float g_part[NCTA*PSZ];
__device__ unsigned g_barcnt = 0;
__device__ unsigned g_bargen = 0;

struct SmemP1 { __half sK[2][KT][STR]; __half sV[2][KT][STR]; };
struct SmemP2 { __half skv[DD][STR]; };
union SmemU { SmemP1 p1; SmemP2 p2; };

__device__ __forceinline__ float phi_f(float x){
    return x > 0.0f ? x + 1.0f : __expf(x);   // elu(x)+1
}
__device__ __forceinline__ uint32_t sptr(const void* p){
    return (uint32_t)__cvta_generic_to_shared(p);
}
__device__ __forceinline__ void ldsm4t(uint32_t d[4], uint32_t addr){
    asm volatile("ldmatrix.sync.aligned.m8n8.x4.trans.shared.b16 {%0,%1,%2,%3}, [%4];"
        : "=r"(d[0]),"=r"(d[1]),"=r"(d[2]),"=r"(d[3]) : "r"(addr));
}
__device__ __forceinline__ void ldsm2t(uint32_t d[2], uint32_t addr){
    asm volatile("ldmatrix.sync.aligned.m8n8.x2.trans.shared.b16 {%0,%1}, [%2];"
        : "=r"(d[0]),"=r"(d[1]) : "r"(addr));
}
__device__ __forceinline__ void mma_f16(float c[4], const uint32_t a[4], const uint32_t b[2]){
    asm volatile("mma.sync.aligned.m16n8k16.row.col.f32.f16.f16.f32 "
        "{%0,%1,%2,%3},{%4,%5,%6,%7},{%8,%9},{%0,%1,%2,%3};"
        : "+f"(c[0]),"+f"(c[1]),"+f"(c[2]),"+f"(c[3])
        : "r"(a[0]),"r"(a[1]),"r"(a[2]),"r"(a[3]),"r"(b[0]),"r"(b[1]));
}
__device__ __forceinline__ uint32_t packphi(float2 f){
    __half2 h = __floats2half2_rn(phi_f(f.x*0.125f), phi_f(f.y*0.125f));
    return *(uint32_t*)&h;
}

__global__ __launch_bounds__(NTHR, 4)
void fused_kernel(const float* __restrict__ Q, const float* __restrict__ K,
                  const float* __restrict__ V, const float* __restrict__ mask,
                  float* __restrict__ O){
    __shared__ __align__(16) SmemU sm;
    int head = blockIdx.x;          // 0..63
    int ch   = blockIdx.y;          // 0..7
    int b    = head / HH;
    int tid  = threadIdx.x;
    int lane = tid & 31, warp = tid >> 5;
    int mg   = warp & 3;            // m-group: d/s rows [16mg,16mg+16)
    int nh   = warp >> 2;           // n-half: 0 -> tiles 0-3, 1 -> tiles 4-7 (+8)
    int gid  = lane >> 2, tig = lane & 3;
    int li   = lane & 7;
    int m0   = mg * 16;
    int bOffBase = nh * 64;         // byte offset of first B n-tile (4 tiles * 16B)

    // ======================= PHASE 1: KV partial =======================
    {
        // pad init for both sV buffers: col64=1, 65..71=0
        for (int i = tid; i < 2*KT*8; i += NTHR){
            int buf = i >= KT*8;
            int j = i - buf*KT*8;
            int r = j >> 3, cc = 64 + (j & 7);
            sm.p1.sV[buf][r][cc] = (cc == 64) ? __float2half(1.0f) : __float2half(0.0f);
        }

        float c[5][4];
        #pragma unroll
        for (int nt=0; nt<5; nt++){ c[nt][0]=0.f; c[nt][1]=0.f; c[nt][2]=0.f; c[nt][3]=0.f; }

        const float* Kb = K + (size_t)head*SS*DD;
        const float* Vb = V + (size_t)head*SS*DD;
        const float* Mb = mask + (size_t)b*SS;
        int s0 = ch * CHUNK;

        // per-thread load coords: 2 (row, c4) pairs per tile (KT*16/NTHR = 2)
        int lr[2], lc4[2];
        #pragma unroll
        for (int j = 0; j < 2; j++){
            int idx = tid + j*NTHR;
            lr[j]  = idx >> 4;
            lc4[j] = idx & 15;
        }

        int aRow = li + ((lane >> 4) << 3);
        int aCol = m0 + (((lane >> 3) & 1) << 3);
        int bRow = li + (((lane >> 3) & 1) << 3);
        uint32_t aBase = sptr(&sm.p1.sK[0][aRow][aCol]);
        uint32_t bBase = sptr(&sm.p1.sV[0][bRow][0]);
        const uint32_t BUFSTRIDE = KT*STR*2;

        float4 kk[2], vv[2];
        float  mm[2];

        // prologue: fetch tile 0
        #pragma unroll
        for (int j = 0; j < 2; j++){
            int row = s0 + lr[j];
            kk[j] = ((const float4*)(Kb + (size_t)row*DD))[lc4[j]];
            vv[j] = ((const float4*)(Vb + (size_t)row*DD))[lc4[j]];
            mm[j] = Mb[row];
        }
        #pragma unroll
        for (int j = 0; j < 2; j++){
            ((__half2*)&sm.p1.sK[0][lr[j]][0])[lc4[j]*2  ] = __floats2half2_rn(phi_f(kk[j].x)*mm[j], phi_f(kk[j].y)*mm[j]);
            ((__half2*)&sm.p1.sK[0][lr[j]][0])[lc4[j]*2+1] = __floats2half2_rn(phi_f(kk[j].z)*mm[j], phi_f(kk[j].w)*mm[j]);
            ((__half2*)&sm.p1.sV[0][lr[j]][0])[lc4[j]*2  ] = __floats2half2_rn(vv[j].x, vv[j].y);
            ((__half2*)&sm.p1.sV[0][lr[j]][0])[lc4[j]*2+1] = __floats2half2_rn(vv[j].z, vv[j].w);
        }
        __syncthreads();

        for (int t = 0; t < NT; t++){
            int buf = t & 1;
            if (t + 1 < NT){
                int sbase = s0 + (t+1)*KT;
                #pragma unroll
                for (int j = 0; j < 2; j++){
                    int row = sbase + lr[j];
                    kk[j] = ((const float4*)(Kb + (size_t)row*DD))[lc4[j]];
                    vv[j] = ((const float4*)(Vb + (size_t)row*DD))[lc4[j]];
                    mm[j] = Mb[row];
                }
            }
            uint32_t aB = aBase + buf*BUFSTRIDE;
            uint32_t bB = bBase + buf*BUFSTRIDE;
            #pragma unroll
            for (int ks = 0; ks < KT/16; ks++){
                uint32_t a[4];
                ldsm4t(a, aB + ks*16*(STR*2));
                #pragma unroll
                for (int j = 0; j < 5; j++){
                    if (j == 4 && nh == 0) break;            // warp-uniform
                    int off = (j == 4) ? 8*16 : bOffBase + j*16;
                    uint32_t bb[2];
                    ldsm2t(bb, bB + ks*16*(STR*2) + off);
                    mma_f16(c[j], a, bb);
                }
            }
            if (t + 1 < NT){
                int nb = buf ^ 1;
                #pragma unroll
                for (int j = 0; j < 2; j++){
                    ((__half2*)&sm.p1.sK[nb][lr[j]][0])[lc4[j]*2  ] = __floats2half2_rn(phi_f(kk[j].x)*mm[j], phi_f(kk[j].y)*mm[j]);
                    ((__half2*)&sm.p1.sK[nb][lr[j]][0])[lc4[j]*2+1] = __floats2half2_rn(phi_f(kk[j].z)*mm[j], phi_f(kk[j].w)*mm[j]);
                    ((__half2*)&sm.p1.sV[nb][lr[j]][0])[lc4[j]*2  ] = __floats2half2_rn(vv[j].x, vv[j].y);
                    ((__half2*)&sm.p1.sV[nb][lr[j]][0])[lc4[j]*2+1] = __floats2half2_rn(vv[j].z, vv[j].w);
                }
                __syncthreads();
            }
        }

        // write partial (plain stores, no atomics)
        float* dst = g_part + (size_t)(head*NCH + ch)*PSZ;
        int r0 = m0 + gid, r1 = r0 + 8;
        int cbase = nh * 32;
        #pragma unroll
        for (int j = 0; j < 4; j++){
            int col = cbase + j*8 + 2*tig;
            dst[r0*DD + col    ] = c[j][0];
            dst[r0*DD + col + 1] = c[j][1];
            dst[r1*DD + col    ] = c[j][2];
            dst[r1*DD + col + 1] = c[j][3];
        }
        if (nh == 1 && tig == 0){
            dst[64*DD + r0] = c[4][0];
            dst[64*DD + r1] = c[4][2];
        }
    }

    // ======================= device-wide barrier =======================
    __threadfence();
    __syncthreads();
    if (tid == 0){
        unsigned gen = atomicAdd(&g_bargen, 0u);
        unsigned ticket = atomicAdd(&g_barcnt, 1u);
        if (ticket == NCTA - 1){
            atomicExch(&g_barcnt, 0u);
            __threadfence();
            atomicAdd(&g_bargen, 1u);
        } else {
            while (atomicAdd(&g_bargen, 0u) == gen) { }
        }
    }
    __syncthreads();
    __threadfence();

    // ======================= PHASE 2: output ===========================
    {
        // reduce 8 partials -> skv (f16), col64=k1, 65..71=0 (one sync, then lock-free)
        const float* pbase = g_part + (size_t)head*NCH*PSZ;
        for (int i = tid; i < 64*16; i += NTHR){
            int r = i >> 4, c4 = i & 15;
            float4 s = make_float4(0.f,0.f,0.f,0.f);
            #pragma unroll
            for (int p = 0; p < NCH; p++){
                float4 f = *(const float4*)(pbase + (size_t)p*PSZ + r*DD + c4*4);
                s.x += f.x; s.y += f.y; s.z += f.z; s.w += f.w;
            }
            ((__half2*)&sm.p2.skv[r][0])[c4*2  ] = __floats2half2_rn(s.x, s.y);
            ((__half2*)&sm.p2.skv[r][0])[c4*2+1] = __floats2half2_rn(s.z, s.w);
        }
        if (tid < 64){
            float s = 0.f;
            #pragma unroll
            for (int p = 0; p < NCH; p++) s += pbase[(size_t)p*PSZ + 64*DD + tid];
            sm.p2.skv[tid][64] = __float2half(s);
        }
        for (int i = tid; i < 64*7; i += NTHR){
            int r = i / 7, cc = 65 + (i % 7);
            sm.p2.skv[r][cc] = __float2half(0.0f);
        }
        __syncthreads();

        int s_base = ch * CHUNK;                 // this CTA owns 512 rows of its head
        const float* Qb = Q + ((size_t)head*SS + s_base)*DD;
        float*       Ob = O + ((size_t)head*SS + s_base)*DD;

        int bRow = li + (((lane >> 3) & 1) << 3);
        uint32_t bBase = sptr(&sm.p2.skv[bRow][0]);

        int r0 = m0 + gid, r1 = r0 + 8;
        int qcol = 2*tig;
        int cbase = nh * 32;

        for (int st = 0; st < 8; st++){
            // register-direct Q fragments: 16 independent float2 LDGs (MLP=16)
            const float* qr0 = Qb + (size_t)(st*64 + r0)*DD;
            const float* qr1 = Qb + (size_t)(st*64 + r1)*DD;
            float2 f0[4], f1[4], f2[4], f3[4];
            #pragma unroll
            for (int ks = 0; ks < 4; ks++){
                f0[ks] = *(const float2*)(qr0 + ks*16 + qcol);
                f1[ks] = *(const float2*)(qr1 + ks*16 + qcol);
                f2[ks] = *(const float2*)(qr0 + ks*16 + qcol + 8);
                f3[ks] = *(const float2*)(qr1 + ks*16 + qcol + 8);
            }
            uint32_t a[4][4];
            #pragma unroll
            for (int ks = 0; ks < 4; ks++){
                a[ks][0] = packphi(f0[ks]);
                a[ks][1] = packphi(f1[ks]);
                a[ks][2] = packphi(f2[ks]);
                a[ks][3] = packphi(f3[ks]);
            }

            float c[5][4];
            #pragma unroll
            for (int nt=0; nt<5; nt++){ c[nt][0]=0.f; c[nt][1]=0.f; c[nt][2]=0.f; c[nt][3]=0.f; }

            #pragma unroll
            for (int ks = 0; ks < 4; ks++){
                #pragma unroll
                for (int j = 0; j < 5; j++){
                    int off = (j == 4) ? 8*16 : bOffBase + j*16;
                    uint32_t bb[2];
                    ldsm2t(bb, bBase + ks*16*(STR*2) + off);
                    mma_f16(c[j], a[ks], bb);
                }
            }

            // tile 8 (computed by both halves) -> per-row normalizer
            float n0 = __shfl_sync(0xffffffffu, c[4][0], lane & 28);
            float n1 = __shfl_sync(0xffffffffu, c[4][2], lane & 28);
            float i0 = 1.0f / (n0 + EPSF);
            float i1 = 1.0f / (n1 + EPSF);

            float* Ot = Ob + (size_t)st*64*DD;
            #pragma unroll
            for (int j = 0; j < 4; j++){
                int col = cbase + j*8 + 2*tig;
                float2 o0; o0.x = c[j][0]*i0; o0.y = c[j][1]*i0;
                float2 o1; o1.x = c[j][2]*i1; o1.y = c[j][3]*i1;
                *(float2*)(Ot + (size_t)r0*DD + col) = o0;
                *(float2*)(Ot + (size_t)r1*DD + col) = o1;
            }
        }
    }
}

extern "C" void kernel_launch(void* const* d_in, const int* in_sizes, int n_in,
                              void* d_out, int out_size){
    const float* Q    = (const float*)d_in[0];
    const float* K    = (const float*)d_in[1];
    const float* V    = (const float*)d_in[2];
    const float* mask = (const float*)d_in[3];
    float* O = (float*)d_out;

    fused_kernel<<<dim3(NHEAD, NCH), NTHR>>>(Q, K, V, mask, O);
}

// round 16
// speedup vs baseline: 1.1754x; 1.1754x over previous
#include <cuda_runtime.h>
#include <cuda_fp16.h>
#include <cstdint>

#define BB 4
#define HH 16
#define SS 4096
#define DD 64
#define NHEAD (BB*HH)        // 64
#define NCH 8
#define CHUNK (SS/NCH)       // 512
#define KT 32                // s-rows per smem tile (double-buffered)
#define NT (CHUNK/KT)        // 16
#define NCTA (NHEAD*NCH)     // 512
#define NTHR 256
#define EPSF 1e-6f
#define STR 72               // padded half cols (144B row stride, conflict-free LDSM)
#define PSZ (65*64)          // partial floats: rows 0-63 kv[d][v], row 64 = k1[d]
#define REDSZ (65*64)        // reduced f16 state per head

// per-(head,chunk) partial results; fully rewritten every launch (no zeroing needed)
__device__ float    g_part[NCTA*PSZ];
__device__ __half   g_red[NHEAD*REDSZ];
__device__ unsigned g_arrive[NHEAD];   // monotonic, replay-safe
__device__ unsigned g_done[NHEAD];     // monotonic, replay-safe

struct SmemP1 { __half sK[2][KT][STR]; __half sV[2][KT][STR]; };
struct SmemP2 { __half skv[DD][STR]; __half sQ[2][64][STR]; };
union SmemU { SmemP1 p1; SmemP2 p2; };

__device__ __forceinline__ float phi_f(float x){
    return x > 0.0f ? x + 1.0f : __expf(x);   // elu(x)+1
}
__device__ __forceinline__ uint32_t sptr(const void* p){
    return (uint32_t)__cvta_generic_to_shared(p);
}
__device__ __forceinline__ void ldsm4t(uint32_t d[4], uint32_t addr){
    asm volatile("ldmatrix.sync.aligned.m8n8.x4.trans.shared.b16 {%0,%1,%2,%3}, [%4];"
        : "=r"(d[0]),"=r"(d[1]),"=r"(d[2]),"=r"(d[3]) : "r"(addr));
}
__device__ __forceinline__ void ldsm4(uint32_t d[4], uint32_t addr){
    asm volatile("ldmatrix.sync.aligned.m8n8.x4.shared.b16 {%0,%1,%2,%3}, [%4];"
        : "=r"(d[0]),"=r"(d[1]),"=r"(d[2]),"=r"(d[3]) : "r"(addr));
}
__device__ __forceinline__ void ldsm2t(uint32_t d[2], uint32_t addr){
    asm volatile("ldmatrix.sync.aligned.m8n8.x2.trans.shared.b16 {%0,%1}, [%2];"
        : "=r"(d[0]),"=r"(d[1]) : "r"(addr));
}
__device__ __forceinline__ void mma_f16(float c[4], const uint32_t a[4], const uint32_t b[2]){
    asm volatile("mma.sync.aligned.m16n8k16.row.col.f32.f16.f16.f32 "
        "{%0,%1,%2,%3},{%4,%5,%6,%7},{%8,%9},{%0,%1,%2,%3};"
        : "+f"(c[0]),"+f"(c[1]),"+f"(c[2]),"+f"(c[3])
        : "r"(a[0]),"r"(a[1]),"r"(a[2]),"r"(a[3]),"r"(b[0]),"r"(b[1]));
}

__global__ __launch_bounds__(NTHR, 4)
void fused_kernel(const float* __restrict__ Q, const float* __restrict__ K,
                  const float* __restrict__ V, const float* __restrict__ mask,
                  float* __restrict__ O){
    __shared__ __align__(16) SmemU sm;
    __shared__ unsigned s_cur, s_red;
    int head = blockIdx.x;          // 0..63
    int ch   = blockIdx.y;          // 0..7
    int b    = head / HH;
    int tid  = threadIdx.x;
    int lane = tid & 31, warp = tid >> 5;
    int mg   = warp & 3;            // m-group: d/s rows [16mg,16mg+16)
    int nh   = warp >> 2;           // n-half: 0 -> tiles 0-3, 1 -> tiles 4-7 (+8)
    int gid  = lane >> 2, tig = lane & 3;
    int li   = lane & 7;
    int m0   = mg * 16;
    int bOffBase = nh * 64;         // byte offset of first B n-tile (4 tiles * 16B)

    if (tid == 0) s_cur = *((volatile unsigned*)&g_done[head]);

    // ======================= PHASE 1: KV partial =======================
    {
        // pad init for both sV buffers: col64=1, 65..71=0
        for (int i = tid; i < 2*KT*8; i += NTHR){
            int buf = i >= KT*8;
            int j = i - buf*KT*8;
            int r = j >> 3, cc = 64 + (j & 7);
            sm.p1.sV[buf][r][cc] = (cc == 64) ? __float2half(1.0f) : __float2half(0.0f);
        }

        float c[5][4];
        #pragma unroll
        for (int nt=0; nt<5; nt++){ c[nt][0]=0.f; c[nt][1]=0.f; c[nt][2]=0.f; c[nt][3]=0.f; }

        const float* Kb = K + (size_t)head*SS*DD;
        const float* Vb = V + (size_t)head*SS*DD;
        const float* Mb = mask + (size_t)b*SS;
        int s0 = ch * CHUNK;

        int lr[2], lc4[2];
        #pragma unroll
        for (int j = 0; j < 2; j++){
            int idx = tid + j*NTHR;
            lr[j]  = idx >> 4;
            lc4[j] = idx & 15;
        }

        int aRow = li + ((lane >> 4) << 3);
        int aCol = m0 + (((lane >> 3) & 1) << 3);
        int bRow = li + (((lane >> 3) & 1) << 3);
        uint32_t aBase = sptr(&sm.p1.sK[0][aRow][aCol]);
        uint32_t bBase = sptr(&sm.p1.sV[0][bRow][0]);
        const uint32_t BUFSTRIDE = KT*STR*2;

        float4 kk[2], vv[2];
        float  mm[2];

        #pragma unroll
        for (int j = 0; j < 2; j++){
            int row = s0 + lr[j];
            kk[j] = ((const float4*)(Kb + (size_t)row*DD))[lc4[j]];
            vv[j] = ((const float4*)(Vb + (size_t)row*DD))[lc4[j]];
            mm[j] = Mb[row];
        }
        #pragma unroll
        for (int j = 0; j < 2; j++){
            ((__half2*)&sm.p1.sK[0][lr[j]][0])[lc4[j]*2  ] = __floats2half2_rn(phi_f(kk[j].x)*mm[j], phi_f(kk[j].y)*mm[j]);
            ((__half2*)&sm.p1.sK[0][lr[j]][0])[lc4[j]*2+1] = __floats2half2_rn(phi_f(kk[j].z)*mm[j], phi_f(kk[j].w)*mm[j]);
            ((__half2*)&sm.p1.sV[0][lr[j]][0])[lc4[j]*2  ] = __floats2half2_rn(vv[j].x, vv[j].y);
            ((__half2*)&sm.p1.sV[0][lr[j]][0])[lc4[j]*2+1] = __floats2half2_rn(vv[j].z, vv[j].w);
        }
        __syncthreads();

        for (int t = 0; t < NT; t++){
            int buf = t & 1;
            if (t + 1 < NT){
                int sbase = s0 + (t+1)*KT;
                #pragma unroll
                for (int j = 0; j < 2; j++){
                    int row = sbase + lr[j];
                    kk[j] = ((const float4*)(Kb + (size_t)row*DD))[lc4[j]];
                    vv[j] = ((const float4*)(Vb + (size_t)row*DD))[lc4[j]];
                    mm[j] = Mb[row];
                }
            }
            uint32_t aB = aBase + buf*BUFSTRIDE;
            uint32_t bB = bBase + buf*BUFSTRIDE;
            #pragma unroll
            for (int ks = 0; ks < KT/16; ks++){
                uint32_t a[4];
                ldsm4t(a, aB + ks*16*(STR*2));
                #pragma unroll
                for (int j = 0; j < 5; j++){
                    if (j == 4 && nh == 0) break;            // warp-uniform
                    int off = (j == 4) ? 8*16 : bOffBase + j*16;
                    uint32_t bb[2];
                    ldsm2t(bb, bB + ks*16*(STR*2) + off);
                    mma_f16(c[j], a, bb);
                }
            }
            if (t + 1 < NT){
                int nb = buf ^ 1;
                #pragma unroll
                for (int j = 0; j < 2; j++){
                    ((__half2*)&sm.p1.sK[nb][lr[j]][0])[lc4[j]*2  ] = __floats2half2_rn(phi_f(kk[j].x)*mm[j], phi_f(kk[j].y)*mm[j]);
                    ((__half2*)&sm.p1.sK[nb][lr[j]][0])[lc4[j]*2+1] = __floats2half2_rn(phi_f(kk[j].z)*mm[j], phi_f(kk[j].w)*mm[j]);
                    ((__half2*)&sm.p1.sV[nb][lr[j]][0])[lc4[j]*2  ] = __floats2half2_rn(vv[j].x, vv[j].y);
                    ((__half2*)&sm.p1.sV[nb][lr[j]][0])[lc4[j]*2+1] = __floats2half2_rn(vv[j].z, vv[j].w);
                }
                __syncthreads();
            }
        }

        // write partial (plain stores, no atomics)
        float* dst = g_part + (size_t)(head*NCH + ch)*PSZ;
        int r0 = m0 + gid, r1 = r0 + 8;
        int cbase = nh * 32;
        #pragma unroll
        for (int j = 0; j < 4; j++){
            int col = cbase + j*8 + 2*tig;
            dst[r0*DD + col    ] = c[j][0];
            dst[r0*DD + col + 1] = c[j][1];
            dst[r1*DD + col    ] = c[j][2];
            dst[r1*DD + col + 1] = c[j][3];
        }
        if (nh == 1 && tig == 0){
            dst[64*DD + r0] = c[4][0];
            dst[64*DD + r1] = c[4][2];
        }
    }

    // ================ per-head arrival; elect reducer ==================
    __threadfence();
    __syncthreads();
    if (tid == 0){
        unsigned t = atomicAdd(&g_arrive[head], 1u);
        s_red = ((t & 7u) == 7u) ? 1u : 0u;
    }
    __syncthreads();
    bool reducer = (s_red != 0u);

    // ======================= PHASE 2: output ===========================
    {
        const float* pbase = g_part + (size_t)head*NCH*PSZ;
        __half* red = g_red + (size_t)head*REDSZ;
        int s_base = ch * CHUNK;
        const float* Qb = Q + ((size_t)head*SS + s_base)*DD;
        float*       Ob = O + ((size_t)head*SS + s_base)*DD;

        if (reducer){
            // fold 8 partials -> smem skv + gmem g_red
            for (int i = tid; i < 64*16; i += NTHR){
                int r = i >> 4, c4 = i & 15;
                float4 s = make_float4(0.f,0.f,0.f,0.f);
                #pragma unroll
                for (int p = 0; p < NCH; p++){
                    float4 f = *(const float4*)(pbase + (size_t)p*PSZ + r*DD + c4*4);
                    s.x += f.x; s.y += f.y; s.z += f.z; s.w += f.w;
                }
                __half2 h0 = __floats2half2_rn(s.x, s.y);
                __half2 h1 = __floats2half2_rn(s.z, s.w);
                ((__half2*)&sm.p2.skv[r][0])[c4*2  ] = h0;
                ((__half2*)&sm.p2.skv[r][0])[c4*2+1] = h1;
                uint2 u; u.x = *(uint32_t*)&h0; u.y = *(uint32_t*)&h1;
                ((uint2*)red)[i] = u;
            }
            if (tid < 64){
                float s = 0.f;
                #pragma unroll
                for (int p = 0; p < NCH; p++) s += pbase[(size_t)p*PSZ + 64*DD + tid];
                __half h = __float2half(s);
                sm.p2.skv[tid][64] = h;
                red[64*64 + tid] = h;
            }
            for (int i = tid; i < 64*7; i += NTHR){
                int r = i / 7, cc = 65 + (i % 7);
                sm.p2.skv[r][cc] = __float2half(0.0f);
            }
            __threadfence();
            __syncthreads();
            if (tid == 0) atomicAdd(&g_done[head], 1u);
            // prefill first Q subtile
            #pragma unroll
            for (int j = 0; j < 4; j++){
                int idx = tid + j*NTHR;
                int r = idx >> 4, c4 = idx & 15;
                float4 q = ((const float4*)(Qb + (size_t)r*DD))[c4];
                ((__half2*)&sm.p2.sQ[0][r][0])[c4*2  ] = __floats2half2_rn(phi_f(q.x*0.125f), phi_f(q.y*0.125f));
                ((__half2*)&sm.p2.sQ[0][r][0])[c4*2+1] = __floats2half2_rn(phi_f(q.z*0.125f), phi_f(q.w*0.125f));
            }
        } else {
            // prefill first Q subtile while waiting (independent of skv)
            #pragma unroll
            for (int j = 0; j < 4; j++){
                int idx = tid + j*NTHR;
                int r = idx >> 4, c4 = idx & 15;
                float4 q = ((const float4*)(Qb + (size_t)r*DD))[c4];
                ((__half2*)&sm.p2.sQ[0][r][0])[c4*2  ] = __floats2half2_rn(phi_f(q.x*0.125f), phi_f(q.y*0.125f));
                ((__half2*)&sm.p2.sQ[0][r][0])[c4*2+1] = __floats2half2_rn(phi_f(q.z*0.125f), phi_f(q.w*0.125f));
            }
            if (tid == 0){
                volatile unsigned* dp = &g_done[head];
                while (*dp == s_cur) { __nanosleep(64); }
            }
            __syncthreads();
            __threadfence();
            // load reduced state (L2-hot, 8.3KB)
            for (int i = tid; i < 64*16; i += NTHR){
                ((uint2*)&sm.p2.skv[i >> 4][0])[i & 15] = ((const uint2*)red)[i];
            }
            if (tid < 64) sm.p2.skv[tid][64] = red[64*64 + tid];
            for (int i = tid; i < 64*7; i += NTHR){
                int r = i / 7, cc = 65 + (i % 7);
                sm.p2.skv[r][cc] = __float2half(0.0f);
            }
        }
        __syncthreads();

        int bRow = li + (((lane >> 3) & 1) << 3);
        int aRow = m0 + li + (((lane >> 3) & 1) << 3);
        int aCol = (lane >> 4) << 3;
        uint32_t aBase = sptr(&sm.p2.sQ[0][aRow][aCol]);
        uint32_t bBase = sptr(&sm.p2.skv[bRow][0]);
        const uint32_t QBUF = 64*STR*2;

        float4 qf[4];
        for (int st = 0; st < 8; st++){
            int buf = st & 1;
            if (st + 1 < 8){
                const float* Qt = Qb + (size_t)(st+1)*64*DD;
                #pragma unroll
                for (int j = 0; j < 4; j++){
                    int idx = tid + j*NTHR;
                    int r = idx >> 4, c4 = idx & 15;
                    qf[j] = ((const float4*)(Qt + (size_t)r*DD))[c4];
                }
            }

            float c[5][4];
            #pragma unroll
            for (int nt=0; nt<5; nt++){ c[nt][0]=0.f; c[nt][1]=0.f; c[nt][2]=0.f; c[nt][3]=0.f; }

            uint32_t aB = aBase + buf*QBUF;
            #pragma unroll
            for (int ks = 0; ks < 4; ks++){
                uint32_t a[4];
                ldsm4(a, aB + ks*16*2);
                #pragma unroll
                for (int j = 0; j < 5; j++){
                    int off = (j == 4) ? 8*16 : bOffBase + j*16;
                    uint32_t bb[2];
                    ldsm2t(bb, bBase + ks*16*(STR*2) + off);
                    mma_f16(c[j], a, bb);
                }
            }

            float n0 = __shfl_sync(0xffffffffu, c[4][0], lane & 28);
            float n1 = __shfl_sync(0xffffffffu, c[4][2], lane & 28);
            float i0 = 1.0f / (n0 + EPSF);
            float i1 = 1.0f / (n1 + EPSF);

            float* Ot = Ob + (size_t)st*64*DD;
            int r0 = m0 + gid, r1 = r0 + 8;
            int cbase = nh * 32;
            #pragma unroll
            for (int j = 0; j < 4; j++){
                int col = cbase + j*8 + 2*tig;
                float2 o0; o0.x = c[j][0]*i0; o0.y = c[j][1]*i0;
                float2 o1; o1.x = c[j][2]*i1; o1.y = c[j][3]*i1;
                *(float2*)(Ot + (size_t)r0*DD + col) = o0;
                *(float2*)(Ot + (size_t)r1*DD + col) = o1;
            }

            if (st + 1 < 8){
                int nb = buf ^ 1;
                #pragma unroll
                for (int j = 0; j < 4; j++){
                    int idx = tid + j*NTHR;
                    int r = idx >> 4, c4 = idx & 15;
                    ((__half2*)&sm.p2.sQ[nb][r][0])[c4*2  ] = __floats2half2_rn(phi_f(qf[j].x*0.125f), phi_f(qf[j].y*0.125f));
                    ((__half2*)&sm.p2.sQ[nb][r][0])[c4*2+1] = __floats2half2_rn(phi_f(qf[j].z*0.125f), phi_f(qf[j].w*0.125f));
                }
                __syncthreads();
            }
        }
    }
}

extern "C" void kernel_launch(void* const* d_in, const int* in_sizes, int n_in,
                              void* d_out, int out_size){
    const float* Q    = (const float*)d_in[0];
    const float* K    = (const float*)d_in[1];
    const float* V    = (const float*)d_in[2];
    const float* mask = (const float*)d_in[3];
    float* O = (float*)d_out;

    fused_kernel<<<dim3(NHEAD, NCH), NTHR>>>(Q, K, V, mask, O);
}